// round 13
// baseline (speedup 1.0000x reference)
#include <cuda_runtime.h>
#include <cuda_bf16.h>
#include <cstdint>

#define D 64
#define K 32
#define VOCAB_MAX 100000

// Scratch (alloc-free rule): bf16 P/Q
__device__ unsigned short g_Pb[(size_t)VOCAB_MAX * D];   // bf16(u2e @ W1a)
__device__ unsigned short g_Qb[(size_t)VOCAB_MAX * D];   // bf16(u2e @ W1b + b1)
__device__ int g_flags[1];   // [0] != 0 -> mask buffer is bytes (else 32-bit words)

// ======================= helpers =======================
__device__ __forceinline__ uint32_t smem_to_u32(const void* p) {
    uint32_t a;
    asm("{ .reg .u64 t; cvta.to.shared.u64 t, %1; cvt.u32.u64 %0, t; }" : "=r"(a) : "l"(p));
    return a;
}
#define CVT_BF16X2_F32(result, a, b) \
    asm("cvt.rn.satfinite.bf16x2.f32 %0, %1, %2;" : "=r"(result) : "f"(b), "f"(a))
#define ADD_BF16X2(r, a, b) \
    asm("add.bf16x2 %0, %1, %2;" : "=r"(r) : "r"(a), "r"(b))
#define MAX_BF16X2(r, a, b) \
    asm("max.bf16x2 %0, %1, %2;" : "=r"(r) : "r"(a), "r"(b))

#define LDMATRIX_X4(r0, r1, r2, r3, addr) \
    asm volatile("ldmatrix.sync.aligned.m8n8.x4.shared.b16 {%0,%1,%2,%3}, [%4];" \
        : "=r"(r0), "=r"(r1), "=r"(r2), "=r"(r3) : "r"(addr))
#define LDMATRIX_X4_TRANS(r0, r1, r2, r3, addr) \
    asm volatile("ldmatrix.sync.aligned.m8n8.x4.trans.shared.b16 {%0,%1,%2,%3}, [%4];" \
        : "=r"(r0), "=r"(r1), "=r"(r2), "=r"(r3) : "r"(addr))

// D (f32) += A (bf16) x B (bf16); C==D accumulate in place
#define MMA16816(d0, d1, d2, d3, a0, a1, a2, a3, b0, b1) \
    asm volatile("mma.sync.aligned.m16n8k16.row.col.f32.bf16.bf16.f32 " \
        "{%0,%1,%2,%3}, {%4,%5,%6,%7}, {%8,%9}, {%0,%1,%2,%3};" \
        : "+f"(d0), "+f"(d1), "+f"(d2), "+f"(d3) \
        : "r"(a0), "r"(a1), "r"(a2), "r"(a3), "r"(b0), "r"(b1))

// A-tile SMEM: row stride 72 bf16 (144B) -> conflict-free ldmatrix
#define ASTRIDE_B 144

// ======================= prep: P/Q (bf16 out) + mask dtype scan =======================
__global__ __launch_bounds__(128) void prep_mma_kernel(const float* __restrict__ u2e,
                                                       const float* __restrict__ W1,
                                                       const float* __restrict__ b1,
                                                       int V,
                                                       const unsigned int* __restrict__ mbuf,
                                                       int n_words) {
    __shared__ __align__(16) unsigned char sA[4][32 * ASTRIDE_B];
    __shared__ __align__(16) unsigned char sW[128 * ASTRIDE_B];  // W1 [128 k][64 n] bf16
    __shared__ float sb1[64];
    int tid = threadIdx.x, warp = tid >> 5, lane = tid & 31;

    // ---- mask dtype scan (byte vs word); 0->1 idempotent across graph replays ----
    {
        int byte_mode = 0;
        for (int i = blockIdx.x * blockDim.x + tid; i < n_words; i += gridDim.x * blockDim.x) {
            unsigned int w = mbuf[i];
            if (w != 0u && w != 1u && w != 0x3f800000u) { byte_mode = 1; break; }
        }
        if (byte_mode) atomicOr(&g_flags[0], 1);
    }

    // ---- stage W1 (bf16, padded rows) ----
    for (int p = tid; p < 128 * 32; p += 128) {
        int r = p >> 5, cp = p & 31;
        uint32_t v;
        CVT_BF16X2_F32(v, W1[(size_t)r * 64 + 2 * cp], W1[(size_t)r * 64 + 2 * cp + 1]);
        *(uint32_t*)(sW + r * ASTRIDE_B + cp * 4) = v;
    }
    if (tid < 64) sb1[tid] = b1[tid];
    __syncthreads();

    int v0 = (blockIdx.x * 4 + warp) * 32;
    int vr = v0 + lane;
    int vc = (vr < V) ? vr : (V - 1);

    // Stage this lane's u2e row as bf16 into the warp's A tile
    {
        const float4* row = (const float4*)(u2e + (size_t)vc * D);
        unsigned char* dst = sA[warp] + lane * ASTRIDE_B;
#pragma unroll
        for (int i = 0; i < 8; i++) {
            float4 f0 = row[2 * i], f1 = row[2 * i + 1];
            uint4 w;
            CVT_BF16X2_F32(w.x, f0.x, f0.y);
            CVT_BF16X2_F32(w.y, f0.z, f0.w);
            CVT_BF16X2_F32(w.z, f1.x, f1.y);
            CVT_BF16X2_F32(w.w, f1.z, f1.w);
            *(uint4*)(dst + i * 16) = w;
        }
    }
    __syncwarp();

    uint32_t af[2][4][4];
    uint32_t a_base = smem_to_u32(sA[warp]);
#pragma unroll
    for (int mt = 0; mt < 2; mt++)
#pragma unroll
        for (int ks = 0; ks < 4; ks++) {
            uint32_t addr = a_base + (mt * 16 + (lane & 15)) * ASTRIDE_B + ks * 32 + (lane >> 4) * 16;
            LDMATRIX_X4(af[mt][ks][0], af[mt][ks][1], af[mt][ks][2], af[mt][ks][3], addr);
        }

    uint32_t w_base = smem_to_u32(sW);
    int j0 = 2 * (lane & 3);
    int r0 = lane >> 2;

#pragma unroll
    for (int half = 0; half < 2; half++) {
        unsigned short* gOut = half ? g_Qb : g_Pb;
#pragma unroll
        for (int nt = 0; nt < 8; nt++) {
            uint32_t b[4][2];
            {
                uint32_t r0b, r1b, r2b, r3b;
                uint32_t addr = w_base + (half * 64 + lane) * ASTRIDE_B + nt * 16;
                LDMATRIX_X4_TRANS(r0b, r1b, r2b, r3b, addr);
                b[0][0] = r0b; b[0][1] = r1b; b[1][0] = r2b; b[1][1] = r3b;
                addr = w_base + (half * 64 + 32 + lane) * ASTRIDE_B + nt * 16;
                LDMATRIX_X4_TRANS(r0b, r1b, r2b, r3b, addr);
                b[2][0] = r0b; b[2][1] = r1b; b[3][0] = r2b; b[3][1] = r3b;
            }
            int j = nt * 8 + j0;
            float init0 = half ? sb1[j] : 0.f;
            float init1 = half ? sb1[j + 1] : 0.f;
#pragma unroll
            for (int mt = 0; mt < 2; mt++) {
                float d0 = init0, d1 = init1, d2 = init0, d3 = init1;
#pragma unroll
                for (int ks = 0; ks < 4; ks++)
                    MMA16816(d0, d1, d2, d3,
                             af[mt][ks][0], af[mt][ks][1], af[mt][ks][2], af[mt][ks][3],
                             b[ks][0], b[ks][1]);
                int ra = v0 + mt * 16 + r0;
                int rb = ra + 8;
                uint32_t wlo, whi;
                CVT_BF16X2_F32(wlo, d0, d1);
                CVT_BF16X2_F32(whi, d2, d3);
                if (ra < V) *(uint32_t*)(gOut + (size_t)ra * D + j) = wlo;
                if (rb < V) *(uint32_t*)(gOut + (size_t)rb * D + j) = whi;
            }
        }
    }
}

// ======================= agg: persistent; full B hoist + mt-outer MMA ==================
// B (W2) fragments FULLY register-resident (no per-node B loads). MMA runs as two
// m-tile passes so af is only 16 regs live -> fits alongside the p4 prefetch pipeline.
__global__ __launch_bounds__(256, 2) void agg_mma_kernel(
    const float* __restrict__ u2e,
    const float* __restrict__ W2, const float* __restrict__ b2,
    const float* __restrict__ W3, const float* __restrict__ b3,
    const int* __restrict__ nodes, const int* __restrict__ neigh_idx,
    const void* __restrict__ maskbuf,
    float* __restrict__ out, int n_nodes) {
    __shared__ __align__(16) unsigned char sA[8][32 * ASTRIDE_B];  // per-warp h1 tiles
    __shared__ __align__(16) unsigned char sW2[64 * ASTRIDE_B];    // W2 staging (bf16)
    __shared__ float sb2[64];
    __shared__ float sW3[64];
    int tid = threadIdx.x, warp = tid >> 5, lane = tid & 31;

    for (int p = tid; p < 64 * 32; p += 256) {
        int r = p >> 5, cp = p & 31;
        uint32_t v;
        CVT_BF16X2_F32(v, W2[(size_t)r * 64 + 2 * cp], W2[(size_t)r * 64 + 2 * cp + 1]);
        *(uint32_t*)(sW2 + r * ASTRIDE_B + cp * 4) = v;
    }
    if (tid < 64) { sb2[tid] = b2[tid]; sW3[tid] = W3[tid]; }
    __syncthreads();

    // ---- FULL B-fragment hoist (loop-invariant W2): 64 registers ----
    uint32_t bf[8][4][2];
    {
        uint32_t w_base = smem_to_u32(sW2);
#pragma unroll
        for (int nt = 0; nt < 8; nt++) {
            uint32_t r0b, r1b, r2b, r3b;
            uint32_t addr = w_base + lane * ASTRIDE_B + nt * 16;
            LDMATRIX_X4_TRANS(r0b, r1b, r2b, r3b, addr);
            bf[nt][0][0] = r0b; bf[nt][0][1] = r1b; bf[nt][1][0] = r2b; bf[nt][1][1] = r3b;
            addr = w_base + (32 + lane) * ASTRIDE_B + nt * 16;
            LDMATRIX_X4_TRANS(r0b, r1b, r2b, r3b, addr);
            bf[nt][2][0] = r0b; bf[nt][2][1] = r1b; bf[nt][3][0] = r2b; bf[nt][3][1] = r3b;
        }
    }

    const float b3f = b3[0];
    const int byte_mode = g_flags[0];
    uint32_t a_base = smem_to_u32(sA[warp]);
    const int j0l = 2 * (lane & 3);
    const int seg = lane & 7;        // 16B segment within a 128B bf16 row
    const int rsub = lane >> 3;      // 0..3 (row within a 4-row load group)
    const int erow_sub = lane >> 4;  // 0..1 (row parity for epilogue)
    const int ecol = (lane & 15) * 4;
    int wg = blockIdx.x * 8 + warp;
    int stride = gridDim.x * 8;

    if (wg >= n_nodes) return;

    // ---- pipeline prologue: front-end for the first node ----
    int idx, m;
    uint4 q4, p4[8];
    {
        int node = nodes[wg];
        idx = neigh_idx[wg * K + lane];
        if (byte_mode)
            m = ((const unsigned char*)maskbuf)[(size_t)wg * K + lane] != 0;
        else
            m = ((const unsigned int*)maskbuf)[(size_t)wg * K + lane] != 0u;
        q4 = *(const uint4*)(g_Qb + (size_t)node * D + seg * 8);
#pragma unroll
        for (int it = 0; it < 8; it++) {
            int ridx = __shfl_sync(0xffffffffu, idx, it * 4 + rsub);
            p4[it] = *(const uint4*)(g_Pb + (size_t)ridx * D + seg * 8);
        }
    }

    for (int n = wg; n < n_nodes; n += stride) {
        // ---- layer 1: consume prefetched P/Q -> relu -> A tile ----
        {
            unsigned char* aw = sA[warp];
#pragma unroll
            for (int it = 0; it < 8; it++) {
                uint4 w;
                ADD_BF16X2(w.x, p4[it].x, q4.x); MAX_BF16X2(w.x, w.x, 0u);
                ADD_BF16X2(w.y, p4[it].y, q4.y); MAX_BF16X2(w.y, w.y, 0u);
                ADD_BF16X2(w.z, p4[it].z, q4.z); MAX_BF16X2(w.z, w.z, 0u);
                ADD_BF16X2(w.w, p4[it].w, q4.w); MAX_BF16X2(w.w, w.w, 0u);
                *(uint4*)(aw + (it * 4 + rsub) * ASTRIDE_B + seg * 16) = w;
            }
        }
        __syncwarp();

        // ---- prefetch next node's front-end (overlaps MMA/softmax/epilogue) ----
        int n2 = n + stride;
        int nc2 = (n2 < n_nodes) ? n2 : n;
        int idx2 = neigh_idx[(size_t)nc2 * K + lane];
        int m2;
        if (byte_mode)
            m2 = ((const unsigned char*)maskbuf)[(size_t)nc2 * K + lane] != 0;
        else
            m2 = ((const unsigned int*)maskbuf)[(size_t)nc2 * K + lane] != 0u;
        int node2 = nodes[nc2];
        uint4 q42 = *(const uint4*)(g_Qb + (size_t)node2 * D + seg * 8);
        uint4 p42[8];
#pragma unroll
        for (int it = 0; it < 8; it++) {
            int ridx = __shfl_sync(0xffffffffu, idx2, it * 4 + rsub);
            p42[it] = *(const uint4*)(g_Pb + (size_t)ridx * D + seg * 8);
        }

        // ---- layers 2+3: mt-outer passes; af streams (16 regs), B from registers ----
        float sp0 = 0.f, sp1 = 0.f, sp2 = 0.f, sp3 = 0.f;
#pragma unroll
        for (int mt = 0; mt < 2; mt++) {
            uint32_t af[4][4];
#pragma unroll
            for (int ks = 0; ks < 4; ks++) {
                uint32_t addr = a_base + (mt * 16 + (lane & 15)) * ASTRIDE_B + ks * 32 + (lane >> 4) * 16;
                LDMATRIX_X4(af[ks][0], af[ks][1], af[ks][2], af[ks][3], addr);
            }
#pragma unroll
            for (int nt = 0; nt < 8; nt++) {
                int j = nt * 8 + j0l;
                float bb0 = sb2[j], bb1 = sb2[j + 1];
                float w30 = sW3[j], w31 = sW3[j + 1];
                float d0 = bb0, d1 = bb1, d2 = bb0, d3 = bb1;
#pragma unroll
                for (int ks = 0; ks < 4; ks++)
                    MMA16816(d0, d1, d2, d3,
                             af[ks][0], af[ks][1], af[ks][2], af[ks][3],
                             bf[nt][ks][0], bf[nt][ks][1]);
                float lo = fmaf(fmaxf(d0, 0.f), w30, fmaf(fmaxf(d1, 0.f), w31, 0.f));
                float hi = fmaf(fmaxf(d2, 0.f), w30, fmaf(fmaxf(d3, 0.f), w31, 0.f));
                if (mt == 0) { sp0 += lo; sp1 += hi; } else { sp2 += lo; sp3 += hi; }
            }
        }

        // ---- score reduction across lanes ----
        sp0 += __shfl_xor_sync(0xffffffffu, sp0, 1); sp0 += __shfl_xor_sync(0xffffffffu, sp0, 2);
        sp1 += __shfl_xor_sync(0xffffffffu, sp1, 1); sp1 += __shfl_xor_sync(0xffffffffu, sp1, 2);
        sp2 += __shfl_xor_sync(0xffffffffu, sp2, 1); sp2 += __shfl_xor_sync(0xffffffffu, sp2, 2);
        sp3 += __shfl_xor_sync(0xffffffffu, sp3, 1); sp3 += __shfl_xor_sync(0xffffffffu, sp3, 2);
        int src = (lane & 7) * 4;
        float v0s = __shfl_sync(0xffffffffu, sp0, src);
        float v1s = __shfl_sync(0xffffffffu, sp1, src);
        float v2s = __shfl_sync(0xffffffffu, sp2, src);
        float v3s = __shfl_sync(0xffffffffu, sp3, src);
        float score = ((lane < 8) ? v0s : (lane < 16) ? v1s : (lane < 24) ? v2s : v3s) + b3f;

        // ---- masked softmax across warp (masked lanes -> att exactly 0) ----
        float sc = m ? score : -1e30f;
        float mx = sc;
#pragma unroll
        for (int o = 16; o; o >>= 1) mx = fmaxf(mx, __shfl_xor_sync(0xffffffffu, mx, o));
        float e = __expf(sc - mx);
        float sum = e;
#pragma unroll
        for (int o = 16; o; o >>= 1) sum += __shfl_xor_sync(0xffffffffu, sum, o);
        float att = __fdividef(e, sum);

        // ---- epilogue, cooperative: out[cols] = sum_r att_r * u2e[idx_r][cols] ----
        float a0 = 0.f, a1 = 0.f, a2 = 0.f, a3 = 0.f;
#pragma unroll
        for (int it = 0; it < 16; it++) {
            int row = it * 2 + erow_sub;
            float attr = __shfl_sync(0xffffffffu, att, row);
            int ridx = __shfl_sync(0xffffffffu, idx, row);
            float4 v = *(const float4*)(u2e + (size_t)ridx * D + ecol);
            a0 = fmaf(attr, v.x, a0);
            a1 = fmaf(attr, v.y, a1);
            a2 = fmaf(attr, v.z, a2);
            a3 = fmaf(attr, v.w, a3);
        }
        a0 += __shfl_xor_sync(0xffffffffu, a0, 16);
        a1 += __shfl_xor_sync(0xffffffffu, a1, 16);
        a2 += __shfl_xor_sync(0xffffffffu, a2, 16);
        a3 += __shfl_xor_sync(0xffffffffu, a3, 16);
        if (lane < 16)
            *(float4*)(out + (size_t)n * D + ecol) = make_float4(a0, a1, a2, a3);

        // ---- rotate pipeline registers ----
        idx = idx2; m = m2; q4 = q42;
#pragma unroll
        for (int it = 0; it < 8; it++) p4[it] = p42[it];
    }
}

// ======================= launch =======================
// Input order (metadata): u2e, W1, b1, W2, b2, W3, b3, nodes, neigh_idx, neigh_mask
extern "C" void kernel_launch(void* const* d_in, const int* in_sizes, int n_in,
                              void* d_out, int out_size) {
    const float* u2e = (const float*)d_in[0];
    const float* W1  = (const float*)d_in[1];
    const float* b1  = (const float*)d_in[2];
    const float* W2  = (const float*)d_in[3];
    const float* b2  = (const float*)d_in[4];
    const float* W3  = (const float*)d_in[5];
    const float* b3  = (const float*)d_in[6];
    const int*   nodes     = (const int*)d_in[7];
    const int*   neigh_idx = (const int*)d_in[8];
    const void*  neigh_mask = d_in[9];
    float* out = (float*)d_out;

    int V = in_sizes[0] / D;
    if (V > VOCAB_MAX) V = VOCAB_MAX;
    int n_nodes = in_sizes[7];
    int n_words = in_sizes[9] / 4;   // safe lower bound under both dtypes

    prep_mma_kernel<<<(V + 127) / 128, 128>>>(u2e, W1, b1, V,
                                              (const unsigned int*)neigh_mask, n_words);
    agg_mma_kernel<<<296, 256>>>(u2e, W2, b2, W3, b3,
                                 nodes, neigh_idx, neigh_mask, out, n_nodes);
}

// round 14
// speedup vs baseline: 1.0632x; 1.0632x over previous
#include <cuda_runtime.h>
#include <cuda_bf16.h>
#include <cstdint>

#define D 64
#define K 32
#define VOCAB_MAX 100000

// Scratch (alloc-free rule): bf16 P/Q
__device__ unsigned short g_Pb[(size_t)VOCAB_MAX * D];   // bf16(u2e @ W1a)
__device__ unsigned short g_Qb[(size_t)VOCAB_MAX * D];   // bf16(u2e @ W1b + b1)
__device__ int g_flags[1];   // [0] != 0 -> mask buffer is bytes (else 32-bit words)

// ======================= helpers =======================
__device__ __forceinline__ uint32_t smem_to_u32(const void* p) {
    uint32_t a;
    asm("{ .reg .u64 t; cvta.to.shared.u64 t, %1; cvt.u32.u64 %0, t; }" : "=r"(a) : "l"(p));
    return a;
}
#define CVT_BF16X2_F32(result, a, b) \
    asm("cvt.rn.satfinite.bf16x2.f32 %0, %1, %2;" : "=r"(result) : "f"(b), "f"(a))
#define ADD_BF16X2(r, a, b) \
    asm("add.bf16x2 %0, %1, %2;" : "=r"(r) : "r"(a), "r"(b))
#define MAX_BF16X2(r, a, b) \
    asm("max.bf16x2 %0, %1, %2;" : "=r"(r) : "r"(a), "r"(b))

#define LDMATRIX_X4(r0, r1, r2, r3, addr) \
    asm volatile("ldmatrix.sync.aligned.m8n8.x4.shared.b16 {%0,%1,%2,%3}, [%4];" \
        : "=r"(r0), "=r"(r1), "=r"(r2), "=r"(r3) : "r"(addr))
#define LDMATRIX_X4_TRANS(r0, r1, r2, r3, addr) \
    asm volatile("ldmatrix.sync.aligned.m8n8.x4.trans.shared.b16 {%0,%1,%2,%3}, [%4];" \
        : "=r"(r0), "=r"(r1), "=r"(r2), "=r"(r3) : "r"(addr))

// D (f32) += A (bf16) x B (bf16); C==D accumulate in place
#define MMA16816(d0, d1, d2, d3, a0, a1, a2, a3, b0, b1) \
    asm volatile("mma.sync.aligned.m16n8k16.row.col.f32.bf16.bf16.f32 " \
        "{%0,%1,%2,%3}, {%4,%5,%6,%7}, {%8,%9}, {%0,%1,%2,%3};" \
        : "+f"(d0), "+f"(d1), "+f"(d2), "+f"(d3) \
        : "r"(a0), "r"(a1), "r"(a2), "r"(a3), "r"(b0), "r"(b1))

// A-tile SMEM: row stride 72 bf16 (144B) -> conflict-free ldmatrix
#define ASTRIDE_B 144

// ======================= prep: P/Q (bf16 out) + mask dtype scan =======================
__global__ __launch_bounds__(128) void prep_mma_kernel(const float* __restrict__ u2e,
                                                       const float* __restrict__ W1,
                                                       const float* __restrict__ b1,
                                                       int V,
                                                       const unsigned int* __restrict__ mbuf,
                                                       int n_words) {
    __shared__ __align__(16) unsigned char sA[4][32 * ASTRIDE_B];
    __shared__ __align__(16) unsigned char sW[128 * ASTRIDE_B];  // W1 [128 k][64 n] bf16
    __shared__ float sb1[64];
    int tid = threadIdx.x, warp = tid >> 5, lane = tid & 31;

    // ---- mask dtype scan (byte vs word); 0->1 idempotent across graph replays ----
    {
        int byte_mode = 0;
        for (int i = blockIdx.x * blockDim.x + tid; i < n_words; i += gridDim.x * blockDim.x) {
            unsigned int w = mbuf[i];
            if (w != 0u && w != 1u && w != 0x3f800000u) { byte_mode = 1; break; }
        }
        if (byte_mode) atomicOr(&g_flags[0], 1);
    }

    // ---- stage W1 (bf16, padded rows) ----
    for (int p = tid; p < 128 * 32; p += 128) {
        int r = p >> 5, cp = p & 31;
        uint32_t v;
        CVT_BF16X2_F32(v, W1[(size_t)r * 64 + 2 * cp], W1[(size_t)r * 64 + 2 * cp + 1]);
        *(uint32_t*)(sW + r * ASTRIDE_B + cp * 4) = v;
    }
    if (tid < 64) sb1[tid] = b1[tid];
    __syncthreads();

    int v0 = (blockIdx.x * 4 + warp) * 32;
    int vr = v0 + lane;
    int vc = (vr < V) ? vr : (V - 1);

    // Stage this lane's u2e row as bf16 into the warp's A tile
    {
        const float4* row = (const float4*)(u2e + (size_t)vc * D);
        unsigned char* dst = sA[warp] + lane * ASTRIDE_B;
#pragma unroll
        for (int i = 0; i < 8; i++) {
            float4 f0 = row[2 * i], f1 = row[2 * i + 1];
            uint4 w;
            CVT_BF16X2_F32(w.x, f0.x, f0.y);
            CVT_BF16X2_F32(w.y, f0.z, f0.w);
            CVT_BF16X2_F32(w.z, f1.x, f1.y);
            CVT_BF16X2_F32(w.w, f1.z, f1.w);
            *(uint4*)(dst + i * 16) = w;
        }
    }
    __syncwarp();

    uint32_t af[2][4][4];
    uint32_t a_base = smem_to_u32(sA[warp]);
#pragma unroll
    for (int mt = 0; mt < 2; mt++)
#pragma unroll
        for (int ks = 0; ks < 4; ks++) {
            uint32_t addr = a_base + (mt * 16 + (lane & 15)) * ASTRIDE_B + ks * 32 + (lane >> 4) * 16;
            LDMATRIX_X4(af[mt][ks][0], af[mt][ks][1], af[mt][ks][2], af[mt][ks][3], addr);
        }

    uint32_t w_base = smem_to_u32(sW);
    int j0 = 2 * (lane & 3);
    int r0 = lane >> 2;

#pragma unroll
    for (int half = 0; half < 2; half++) {
        unsigned short* gOut = half ? g_Qb : g_Pb;
#pragma unroll
        for (int nt = 0; nt < 8; nt++) {
            uint32_t b[4][2];
            {
                uint32_t r0b, r1b, r2b, r3b;
                uint32_t addr = w_base + (half * 64 + lane) * ASTRIDE_B + nt * 16;
                LDMATRIX_X4_TRANS(r0b, r1b, r2b, r3b, addr);
                b[0][0] = r0b; b[0][1] = r1b; b[1][0] = r2b; b[1][1] = r3b;
                addr = w_base + (half * 64 + 32 + lane) * ASTRIDE_B + nt * 16;
                LDMATRIX_X4_TRANS(r0b, r1b, r2b, r3b, addr);
                b[2][0] = r0b; b[2][1] = r1b; b[3][0] = r2b; b[3][1] = r3b;
            }
            int j = nt * 8 + j0;
            float init0 = half ? sb1[j] : 0.f;
            float init1 = half ? sb1[j + 1] : 0.f;
#pragma unroll
            for (int mt = 0; mt < 2; mt++) {
                float d0 = init0, d1 = init1, d2 = init0, d3 = init1;
#pragma unroll
                for (int ks = 0; ks < 4; ks++)
                    MMA16816(d0, d1, d2, d3,
                             af[mt][ks][0], af[mt][ks][1], af[mt][ks][2], af[mt][ks][3],
                             b[ks][0], b[ks][1]);
                int ra = v0 + mt * 16 + r0;
                int rb = ra + 8;
                uint32_t wlo, whi;
                CVT_BF16X2_F32(wlo, d0, d1);
                CVT_BF16X2_F32(whi, d2, d3);
                if (ra < V) *(uint32_t*)(gOut + (size_t)ra * D + j) = wlo;
                if (rb < V) *(uint32_t*)(gOut + (size_t)rb * D + j) = whi;
            }
        }
    }
}

// ======================= agg: persistent; software-pipelined gathers ====================
// R12 structure (best known) + DISTRIBUTED softmax: no score redistribution, softmax
// runs on 4-scores-per-lane with 3+3 shfl chain instead of 1+5+5.
__global__ __launch_bounds__(256, 2) void agg_mma_kernel(
    const float* __restrict__ u2e,
    const float* __restrict__ W2, const float* __restrict__ b2,
    const float* __restrict__ W3, const float* __restrict__ b3,
    const int* __restrict__ nodes, const int* __restrict__ neigh_idx,
    const void* __restrict__ maskbuf,
    float* __restrict__ out, int n_nodes) {
    __shared__ __align__(16) unsigned char sA[8][32 * ASTRIDE_B];  // per-warp h1 tiles
    __shared__ __align__(16) unsigned char sW2[64 * ASTRIDE_B];    // W2 staging (bf16)
    __shared__ float sb2[64];
    __shared__ float sW3[64];
    int tid = threadIdx.x, warp = tid >> 5, lane = tid & 31;

    for (int p = tid; p < 64 * 32; p += 256) {
        int r = p >> 5, cp = p & 31;
        uint32_t v;
        CVT_BF16X2_F32(v, W2[(size_t)r * 64 + 2 * cp], W2[(size_t)r * 64 + 2 * cp + 1]);
        *(uint32_t*)(sW2 + r * ASTRIDE_B + cp * 4) = v;
    }
    if (tid < 64) { sb2[tid] = b2[tid]; sW3[tid] = W3[tid]; }
    __syncthreads();

    uint32_t w_base = smem_to_u32(sW2);

    // ---- hoist B fragments for n-tiles 0..3 only (register budget) ----
    uint32_t bfh[4][4][2];
#pragma unroll
    for (int nt = 0; nt < 4; nt++) {
        uint32_t r0b, r1b, r2b, r3b;
        uint32_t addr = w_base + lane * ASTRIDE_B + nt * 16;
        LDMATRIX_X4_TRANS(r0b, r1b, r2b, r3b, addr);
        bfh[nt][0][0] = r0b; bfh[nt][0][1] = r1b; bfh[nt][1][0] = r2b; bfh[nt][1][1] = r3b;
        addr = w_base + (32 + lane) * ASTRIDE_B + nt * 16;
        LDMATRIX_X4_TRANS(r0b, r1b, r2b, r3b, addr);
        bfh[nt][2][0] = r0b; bfh[nt][2][1] = r1b; bfh[nt][3][0] = r2b; bfh[nt][3][1] = r3b;
    }

    const int byte_mode = g_flags[0];
    uint32_t a_base = smem_to_u32(sA[warp]);
    const int j0l = 2 * (lane & 3);
    const int seg = lane & 7;        // 16B segment within a 128B bf16 row
    const int rsub = lane >> 3;      // 0..3 (row within a 4-row load group)
    const int erow_sub = lane >> 4;  // 0..1 (row parity for epilogue)
    const int ecol = (lane & 15) * 4;
    const int rbase = lane >> 2;     // base row this lane's scores belong to
    int wg = blockIdx.x * 8 + warp;
    int stride = gridDim.x * 8;

    if (wg >= n_nodes) return;

    // ---- pipeline prologue: front-end for the first node ----
    int idx, m;
    uint4 q4, p4[8];
    {
        int node = nodes[wg];
        idx = neigh_idx[wg * K + lane];
        if (byte_mode)
            m = ((const unsigned char*)maskbuf)[(size_t)wg * K + lane] != 0;
        else
            m = ((const unsigned int*)maskbuf)[(size_t)wg * K + lane] != 0u;
        q4 = *(const uint4*)(g_Qb + (size_t)node * D + seg * 8);
#pragma unroll
        for (int it = 0; it < 8; it++) {
            int ridx = __shfl_sync(0xffffffffu, idx, it * 4 + rsub);
            p4[it] = *(const uint4*)(g_Pb + (size_t)ridx * D + seg * 8);
        }
    }

    for (int n = wg; n < n_nodes; n += stride) {
        // ---- layer 1: consume prefetched P/Q -> relu -> A tile ----
        {
            unsigned char* aw = sA[warp];
#pragma unroll
            for (int it = 0; it < 8; it++) {
                uint4 w;
                ADD_BF16X2(w.x, p4[it].x, q4.x); MAX_BF16X2(w.x, w.x, 0u);
                ADD_BF16X2(w.y, p4[it].y, q4.y); MAX_BF16X2(w.y, w.y, 0u);
                ADD_BF16X2(w.z, p4[it].z, q4.z); MAX_BF16X2(w.z, w.z, 0u);
                ADD_BF16X2(w.w, p4[it].w, q4.w); MAX_BF16X2(w.w, w.w, 0u);
                *(uint4*)(aw + (it * 4 + rsub) * ASTRIDE_B + seg * 16) = w;
            }
        }
        __syncwarp();

        // ---- prefetch next node's front-end (overlaps MMA/softmax/epilogue) ----
        int n2 = n + stride;
        int nc2 = (n2 < n_nodes) ? n2 : n;
        int idx2 = neigh_idx[(size_t)nc2 * K + lane];
        int m2;
        if (byte_mode)
            m2 = ((const unsigned char*)maskbuf)[(size_t)nc2 * K + lane] != 0;
        else
            m2 = ((const unsigned int*)maskbuf)[(size_t)nc2 * K + lane] != 0u;
        int node2 = nodes[nc2];
        uint4 q42 = *(const uint4*)(g_Qb + (size_t)node2 * D + seg * 8);
        uint4 p42[8];
#pragma unroll
        for (int it = 0; it < 8; it++) {
            int ridx = __shfl_sync(0xffffffffu, idx2, it * 4 + rsub);
            p42[it] = *(const uint4*)(g_Pb + (size_t)ridx * D + seg * 8);
        }

        // ---- A fragments (2 m-tiles x 4 k-steps) ----
        uint32_t af[2][4][4];
#pragma unroll
        for (int mt = 0; mt < 2; mt++)
#pragma unroll
            for (int ks = 0; ks < 4; ks++) {
                uint32_t addr = a_base + (mt * 16 + (lane & 15)) * ASTRIDE_B + ks * 32 + (lane >> 4) * 16;
                LDMATRIX_X4(af[mt][ks][0], af[mt][ks][1], af[mt][ks][2], af[mt][ks][3], addr);
            }

        // ---- layer 2 (HMMA) + layer 3 folded per n-tile ----
        float sp0 = 0.f, sp1 = 0.f, sp2 = 0.f, sp3 = 0.f;
#pragma unroll
        for (int nt = 0; nt < 8; nt++) {
            uint32_t b[4][2];
            if (nt < 4) {
#pragma unroll
                for (int ks = 0; ks < 4; ks++) { b[ks][0] = bfh[nt][ks][0]; b[ks][1] = bfh[nt][ks][1]; }
            } else {
                uint32_t r0b, r1b, r2b, r3b;
                uint32_t addr = w_base + lane * ASTRIDE_B + nt * 16;
                LDMATRIX_X4_TRANS(r0b, r1b, r2b, r3b, addr);
                b[0][0] = r0b; b[0][1] = r1b; b[1][0] = r2b; b[1][1] = r3b;
                addr = w_base + (32 + lane) * ASTRIDE_B + nt * 16;
                LDMATRIX_X4_TRANS(r0b, r1b, r2b, r3b, addr);
                b[2][0] = r0b; b[2][1] = r1b; b[3][0] = r2b; b[3][1] = r3b;
            }
            int j = nt * 8 + j0l;
            float bb0 = sb2[j], bb1 = sb2[j + 1];
            float w30 = sW3[j], w31 = sW3[j + 1];
#pragma unroll
            for (int mt = 0; mt < 2; mt++) {
                float d0 = bb0, d1 = bb1, d2 = bb0, d3 = bb1;
#pragma unroll
                for (int ks = 0; ks < 4; ks++)
                    MMA16816(d0, d1, d2, d3,
                             af[mt][ks][0], af[mt][ks][1], af[mt][ks][2], af[mt][ks][3],
                             b[ks][0], b[ks][1]);
                float lo = fmaf(fmaxf(d0, 0.f), w30, fmaf(fmaxf(d1, 0.f), w31, 0.f));
                float hi = fmaf(fmaxf(d2, 0.f), w30, fmaf(fmaxf(d3, 0.f), w31, 0.f));
                if (mt == 0) { sp0 += lo; sp1 += hi; } else { sp2 += lo; sp3 += hi; }
            }
        }

        // ---- early-issue first half of epilogue E gather (depends only on idx) ----
        float4 ev[8];
#pragma unroll
        for (int it = 0; it < 8; it++) {
            int row = it * 2 + erow_sub;
            int ridx = __shfl_sync(0xffffffffu, idx, row);
            ev[it] = *(const float4*)(u2e + (size_t)ridx * D + ecol);
        }

        // ---- finish per-row scores: reduce over the 4 lanes sharing each row ----
        // After this, lane holds scores of rows rbase+{0,8,16,24} in sp0..sp3
        // (replicated across the 4 lanes of its group). b3 is softmax-invariant: omitted.
        sp0 += __shfl_xor_sync(0xffffffffu, sp0, 1); sp0 += __shfl_xor_sync(0xffffffffu, sp0, 2);
        sp1 += __shfl_xor_sync(0xffffffffu, sp1, 1); sp1 += __shfl_xor_sync(0xffffffffu, sp1, 2);
        sp2 += __shfl_xor_sync(0xffffffffu, sp2, 1); sp2 += __shfl_xor_sync(0xffffffffu, sp2, 2);
        sp3 += __shfl_xor_sync(0xffffffffu, sp3, 1); sp3 += __shfl_xor_sync(0xffffffffu, sp3, 2);

        // ---- distributed masked softmax (no redistribution) ----
        unsigned int mask32 = __ballot_sync(0xffffffffu, m);
        float s0 = ((mask32 >> rbase) & 1u)        ? sp0 : -1e30f;
        float s1 = ((mask32 >> (rbase + 8)) & 1u)  ? sp1 : -1e30f;
        float s2 = ((mask32 >> (rbase + 16)) & 1u) ? sp2 : -1e30f;
        float s3 = ((mask32 >> (rbase + 24)) & 1u) ? sp3 : -1e30f;
        float mx = fmaxf(fmaxf(s0, s1), fmaxf(s2, s3));
        mx = fmaxf(mx, __shfl_xor_sync(0xffffffffu, mx, 4));
        mx = fmaxf(mx, __shfl_xor_sync(0xffffffffu, mx, 8));
        mx = fmaxf(mx, __shfl_xor_sync(0xffffffffu, mx, 16));
        float e0 = __expf(s0 - mx), e1 = __expf(s1 - mx);
        float e2 = __expf(s2 - mx), e3 = __expf(s3 - mx);
        float ssum = (e0 + e1) + (e2 + e3);
        ssum += __shfl_xor_sync(0xffffffffu, ssum, 4);
        ssum += __shfl_xor_sync(0xffffffffu, ssum, 8);
        ssum += __shfl_xor_sync(0xffffffffu, ssum, 16);
        float inv = __fdividef(1.f, ssum);
        float att0 = e0 * inv, att1 = e1 * inv, att2 = e2 * inv, att3 = e3 * inv;
        // att_j = attention of row rbase + 8*j; valid on all 4 lanes of the group.

        // ---- epilogue: consume prefetched rows 0..15, then gather rows 16..31 ----
        // att for row r lives on lanes 4*(r&7).. as att{r>>3}; oct = it>>2 is compile-time.
        float a0 = 0.f, a1 = 0.f, a2 = 0.f, a3 = 0.f;
#pragma unroll
        for (int it = 0; it < 8; it++) {
            const int oct = it >> 2;                       // 0 or 1 (rows 0..15)
            float att_oct = (oct == 0) ? att0 : att1;
            int row = it * 2 + erow_sub;
            float attr = __shfl_sync(0xffffffffu, att_oct, (row & 7) * 4);
            a0 = fmaf(attr, ev[it].x, a0);
            a1 = fmaf(attr, ev[it].y, a1);
            a2 = fmaf(attr, ev[it].z, a2);
            a3 = fmaf(attr, ev[it].w, a3);
        }
#pragma unroll
        for (int it = 8; it < 16; it++) {
            const int oct = it >> 2;                       // 2 or 3 (rows 16..31)
            float att_oct = (oct == 2) ? att2 : att3;
            int row = it * 2 + erow_sub;
            float attr = __shfl_sync(0xffffffffu, att_oct, (row & 7) * 4);
            int ridx = __shfl_sync(0xffffffffu, idx, row);
            float4 v = *(const float4*)(u2e + (size_t)ridx * D + ecol);
            a0 = fmaf(attr, v.x, a0);
            a1 = fmaf(attr, v.y, a1);
            a2 = fmaf(attr, v.z, a2);
            a3 = fmaf(attr, v.w, a3);
        }
        a0 += __shfl_xor_sync(0xffffffffu, a0, 16);
        a1 += __shfl_xor_sync(0xffffffffu, a1, 16);
        a2 += __shfl_xor_sync(0xffffffffu, a2, 16);
        a3 += __shfl_xor_sync(0xffffffffu, a3, 16);
        if (lane < 16)
            *(float4*)(out + (size_t)n * D + ecol) = make_float4(a0, a1, a2, a3);

        // ---- rotate pipeline registers ----
        idx = idx2; m = m2; q4 = q42;
#pragma unroll
        for (int it = 0; it < 8; it++) p4[it] = p42[it];
    }
}

// ======================= launch =======================
// Input order (metadata): u2e, W1, b1, W2, b2, W3, b3, nodes, neigh_idx, neigh_mask
extern "C" void kernel_launch(void* const* d_in, const int* in_sizes, int n_in,
                              void* d_out, int out_size) {
    const float* u2e = (const float*)d_in[0];
    const float* W1  = (const float*)d_in[1];
    const float* b1  = (const float*)d_in[2];
    const float* W2  = (const float*)d_in[3];
    const float* b2  = (const float*)d_in[4];
    const float* W3  = (const float*)d_in[5];
    const float* b3  = (const float*)d_in[6];
    const int*   nodes     = (const int*)d_in[7];
    const int*   neigh_idx = (const int*)d_in[8];
    const void*  neigh_mask = d_in[9];
    float* out = (float*)d_out;

    int V = in_sizes[0] / D;
    if (V > VOCAB_MAX) V = VOCAB_MAX;
    int n_nodes = in_sizes[7];
    int n_words = in_sizes[9] / 4;   // safe lower bound under both dtypes

    prep_mma_kernel<<<(V + 127) / 128, 128>>>(u2e, W1, b1, V,
                                              (const unsigned int*)neigh_mask, n_words);
    agg_mma_kernel<<<296, 256>>>(u2e, W2, b2, W3, b3,
                                 nodes, neigh_idx, neigh_mask, out, n_nodes);
}

// round 15
// speedup vs baseline: 1.1427x; 1.0748x over previous
#include <cuda_runtime.h>
#include <cuda_bf16.h>
#include <cstdint>

#define D 64
#define K 32
#define VOCAB_MAX 100000

// Scratch (alloc-free rule): bf16 P/Q
__device__ unsigned short g_Pb[(size_t)VOCAB_MAX * D];   // bf16(u2e @ W1a)
__device__ unsigned short g_Qb[(size_t)VOCAB_MAX * D];   // bf16(u2e @ W1b + b1)
__device__ int g_flags[1];   // [0] != 0 -> mask buffer is bytes (else 32-bit words)

// ======================= helpers =======================
__device__ __forceinline__ uint32_t smem_to_u32(const void* p) {
    uint32_t a;
    asm("{ .reg .u64 t; cvta.to.shared.u64 t, %1; cvt.u32.u64 %0, t; }" : "=r"(a) : "l"(p));
    return a;
}
#define CVT_BF16X2_F32(result, a, b) \
    asm("cvt.rn.satfinite.bf16x2.f32 %0, %1, %2;" : "=r"(result) : "f"(b), "f"(a))
#define ADD_BF16X2(r, a, b) \
    asm("add.bf16x2 %0, %1, %2;" : "=r"(r) : "r"(a), "r"(b))
#define MAX_BF16X2(r, a, b) \
    asm("max.bf16x2 %0, %1, %2;" : "=r"(r) : "r"(a), "r"(b))

#define LDMATRIX_X4(r0, r1, r2, r3, addr) \
    asm volatile("ldmatrix.sync.aligned.m8n8.x4.shared.b16 {%0,%1,%2,%3}, [%4];" \
        : "=r"(r0), "=r"(r1), "=r"(r2), "=r"(r3) : "r"(addr))
#define LDMATRIX_X4_TRANS(r0, r1, r2, r3, addr) \
    asm volatile("ldmatrix.sync.aligned.m8n8.x4.trans.shared.b16 {%0,%1,%2,%3}, [%4];" \
        : "=r"(r0), "=r"(r1), "=r"(r2), "=r"(r3) : "r"(addr))

// D (f32) += A (bf16) x B (bf16); C==D accumulate in place
#define MMA16816(d0, d1, d2, d3, a0, a1, a2, a3, b0, b1) \
    asm volatile("mma.sync.aligned.m16n8k16.row.col.f32.bf16.bf16.f32 " \
        "{%0,%1,%2,%3}, {%4,%5,%6,%7}, {%8,%9}, {%0,%1,%2,%3};" \
        : "+f"(d0), "+f"(d1), "+f"(d2), "+f"(d3) \
        : "r"(a0), "r"(a1), "r"(a2), "r"(a3), "r"(b0), "r"(b1))

// A-tile SMEM: row stride 72 bf16 (144B) -> conflict-free ldmatrix
#define ASTRIDE_B 144

// ======================= prep: P/Q (bf16 out) + mask dtype scan =======================
// Cooperative I/O version: block-contiguous A loads (4 lines/instr) and SMEM-staged
// contiguous stores. Math identical to previous rounds -> bit-identical P/Q.
__global__ __launch_bounds__(128) void prep_mma_kernel(const float* __restrict__ u2e,
                                                       const float* __restrict__ W1,
                                                       const float* __restrict__ b1,
                                                       int V,
                                                       const unsigned int* __restrict__ mbuf,
                                                       int n_words) {
    __shared__ __align__(16) unsigned char sA[4][32 * ASTRIDE_B];
    __shared__ __align__(16) unsigned char sW[128 * ASTRIDE_B];  // W1 [128 k][64 n] bf16
    __shared__ float sb1[64];
    int tid = threadIdx.x, warp = tid >> 5, lane = tid & 31;

    // ---- mask dtype scan (byte vs word); 0->1 idempotent across graph replays ----
    {
        int byte_mode = 0;
        for (int i = blockIdx.x * blockDim.x + tid; i < n_words; i += gridDim.x * blockDim.x) {
            unsigned int w = mbuf[i];
            if (w != 0u && w != 1u && w != 0x3f800000u) { byte_mode = 1; break; }
        }
        if (byte_mode) atomicOr(&g_flags[0], 1);
    }

    // ---- stage W1 (bf16, padded rows) ----
    for (int p = tid; p < 128 * 32; p += 128) {
        int r = p >> 5, cp = p & 31;
        uint32_t v;
        CVT_BF16X2_F32(v, W1[(size_t)r * 64 + 2 * cp], W1[(size_t)r * 64 + 2 * cp + 1]);
        *(uint32_t*)(sW + r * ASTRIDE_B + cp * 4) = v;
    }
    if (tid < 64) sb1[tid] = b1[tid];

    // ---- cooperative A staging: block's 128 rows loaded as one contiguous stream ----
    // chunk i: row = i/16, 16B segment = i%16; consecutive threads -> consecutive 16B.
    int blk_v0 = blockIdx.x * 128;
    for (int i = tid; i < 128 * 16; i += 128) {
        int row = i >> 4;
        int seg = i & 15;
        int grow = blk_v0 + row;
        if (grow >= V) grow = V - 1;
        float4 f = *(const float4*)(u2e + (size_t)grow * D + seg * 4);
        uint2 w;
        CVT_BF16X2_F32(w.x, f.x, f.y);
        CVT_BF16X2_F32(w.y, f.z, f.w);
        *(uint2*)(sA[row >> 5] + (row & 31) * ASTRIDE_B + seg * 8) = w;
    }
    __syncthreads();

    int v0 = blk_v0 + warp * 32;

    // ---- A fragments: 2 m-tiles x 4 k-steps ----
    uint32_t af[2][4][4];
    uint32_t a_base = smem_to_u32(sA[warp]);
#pragma unroll
    for (int mt = 0; mt < 2; mt++)
#pragma unroll
        for (int ks = 0; ks < 4; ks++) {
            uint32_t addr = a_base + (mt * 16 + (lane & 15)) * ASTRIDE_B + ks * 32 + (lane >> 4) * 16;
            LDMATRIX_X4(af[mt][ks][0], af[mt][ks][1], af[mt][ks][2], af[mt][ks][3], addr);
        }
    __syncwarp();   // own tile free for reuse below (only this warp touches it now)

    uint32_t w_base = smem_to_u32(sW);
    int j0 = 2 * (lane & 3);
    int r0 = lane >> 2;

#pragma unroll
    for (int half = 0; half < 2; half++) {
        unsigned short* gOut = half ? g_Qb : g_Pb;
        // compute + stage fragments into own sA tile (conflict-free STS.32)
#pragma unroll
        for (int nt = 0; nt < 8; nt++) {
            uint32_t b[4][2];
            {
                uint32_t r0b, r1b, r2b, r3b;
                uint32_t addr = w_base + (half * 64 + lane) * ASTRIDE_B + nt * 16;
                LDMATRIX_X4_TRANS(r0b, r1b, r2b, r3b, addr);
                b[0][0] = r0b; b[0][1] = r1b; b[1][0] = r2b; b[1][1] = r3b;
                addr = w_base + (half * 64 + 32 + lane) * ASTRIDE_B + nt * 16;
                LDMATRIX_X4_TRANS(r0b, r1b, r2b, r3b, addr);
                b[2][0] = r0b; b[2][1] = r1b; b[3][0] = r2b; b[3][1] = r3b;
            }
            int j = nt * 8 + j0;
            float init0 = half ? sb1[j] : 0.f;
            float init1 = half ? sb1[j + 1] : 0.f;
#pragma unroll
            for (int mt = 0; mt < 2; mt++) {
                float d0 = init0, d1 = init1, d2 = init0, d3 = init1;
#pragma unroll
                for (int ks = 0; ks < 4; ks++)
                    MMA16816(d0, d1, d2, d3,
                             af[mt][ks][0], af[mt][ks][1], af[mt][ks][2], af[mt][ks][3],
                             b[ks][0], b[ks][1]);
                uint32_t wlo, whi;
                CVT_BF16X2_F32(wlo, d0, d1);
                CVT_BF16X2_F32(whi, d2, d3);
                *(uint32_t*)(sA[warp] + (mt * 16 + r0) * ASTRIDE_B + nt * 16 + (lane & 3) * 4) = wlo;
                *(uint32_t*)(sA[warp] + (mt * 16 + r0 + 8) * ASTRIDE_B + nt * 16 + (lane & 3) * 4) = whi;
            }
        }
        __syncwarp();
        // cooperative contiguous store: 32 rows x 128B from stride-144 tile -> global
        for (int i = lane; i < 256; i += 32) {
            int row = i >> 3;
            int seg = i & 7;
            uint4 v = *(uint4*)(sA[warp] + row * ASTRIDE_B + seg * 16);
            int grow = v0 + row;
            if (grow < V)
                *(uint4*)(gOut + (size_t)grow * D + seg * 8) = v;
        }
        __syncwarp();
    }
}

// ======================= agg: persistent; software-pipelined gathers ====================
// R14 (best known): half-B hoist, register P-prefetch pipeline, early-ev epilogue,
// DISTRIBUTED masked softmax. Unchanged this round.
__global__ __launch_bounds__(256, 2) void agg_mma_kernel(
    const float* __restrict__ u2e,
    const float* __restrict__ W2, const float* __restrict__ b2,
    const float* __restrict__ W3, const float* __restrict__ b3,
    const int* __restrict__ nodes, const int* __restrict__ neigh_idx,
    const void* __restrict__ maskbuf,
    float* __restrict__ out, int n_nodes) {
    __shared__ __align__(16) unsigned char sA[8][32 * ASTRIDE_B];  // per-warp h1 tiles
    __shared__ __align__(16) unsigned char sW2[64 * ASTRIDE_B];    // W2 staging (bf16)
    __shared__ float sb2[64];
    __shared__ float sW3[64];
    int tid = threadIdx.x, warp = tid >> 5, lane = tid & 31;

    for (int p = tid; p < 64 * 32; p += 256) {
        int r = p >> 5, cp = p & 31;
        uint32_t v;
        CVT_BF16X2_F32(v, W2[(size_t)r * 64 + 2 * cp], W2[(size_t)r * 64 + 2 * cp + 1]);
        *(uint32_t*)(sW2 + r * ASTRIDE_B + cp * 4) = v;
    }
    if (tid < 64) { sb2[tid] = b2[tid]; sW3[tid] = W3[tid]; }
    __syncthreads();

    uint32_t w_base = smem_to_u32(sW2);

    // ---- hoist B fragments for n-tiles 0..3 only (register budget) ----
    uint32_t bfh[4][4][2];
#pragma unroll
    for (int nt = 0; nt < 4; nt++) {
        uint32_t r0b, r1b, r2b, r3b;
        uint32_t addr = w_base + lane * ASTRIDE_B + nt * 16;
        LDMATRIX_X4_TRANS(r0b, r1b, r2b, r3b, addr);
        bfh[nt][0][0] = r0b; bfh[nt][0][1] = r1b; bfh[nt][1][0] = r2b; bfh[nt][1][1] = r3b;
        addr = w_base + (32 + lane) * ASTRIDE_B + nt * 16;
        LDMATRIX_X4_TRANS(r0b, r1b, r2b, r3b, addr);
        bfh[nt][2][0] = r0b; bfh[nt][2][1] = r1b; bfh[nt][3][0] = r2b; bfh[nt][3][1] = r3b;
    }

    const int byte_mode = g_flags[0];
    uint32_t a_base = smem_to_u32(sA[warp]);
    const int j0l = 2 * (lane & 3);
    const int seg = lane & 7;        // 16B segment within a 128B bf16 row
    const int rsub = lane >> 3;      // 0..3 (row within a 4-row load group)
    const int erow_sub = lane >> 4;  // 0..1 (row parity for epilogue)
    const int ecol = (lane & 15) * 4;
    const int rbase = lane >> 2;     // base row this lane's scores belong to
    int wg = blockIdx.x * 8 + warp;
    int stride = gridDim.x * 8;

    if (wg >= n_nodes) return;

    // ---- pipeline prologue: front-end for the first node ----
    int idx, m;
    uint4 q4, p4[8];
    {
        int node = nodes[wg];
        idx = neigh_idx[wg * K + lane];
        if (byte_mode)
            m = ((const unsigned char*)maskbuf)[(size_t)wg * K + lane] != 0;
        else
            m = ((const unsigned int*)maskbuf)[(size_t)wg * K + lane] != 0u;
        q4 = *(const uint4*)(g_Qb + (size_t)node * D + seg * 8);
#pragma unroll
        for (int it = 0; it < 8; it++) {
            int ridx = __shfl_sync(0xffffffffu, idx, it * 4 + rsub);
            p4[it] = *(const uint4*)(g_Pb + (size_t)ridx * D + seg * 8);
        }
    }

    for (int n = wg; n < n_nodes; n += stride) {
        // ---- layer 1: consume prefetched P/Q -> relu -> A tile ----
        {
            unsigned char* aw = sA[warp];
#pragma unroll
            for (int it = 0; it < 8; it++) {
                uint4 w;
                ADD_BF16X2(w.x, p4[it].x, q4.x); MAX_BF16X2(w.x, w.x, 0u);
                ADD_BF16X2(w.y, p4[it].y, q4.y); MAX_BF16X2(w.y, w.y, 0u);
                ADD_BF16X2(w.z, p4[it].z, q4.z); MAX_BF16X2(w.z, w.z, 0u);
                ADD_BF16X2(w.w, p4[it].w, q4.w); MAX_BF16X2(w.w, w.w, 0u);
                *(uint4*)(aw + (it * 4 + rsub) * ASTRIDE_B + seg * 16) = w;
            }
        }
        __syncwarp();

        // ---- prefetch next node's front-end (overlaps MMA/softmax/epilogue) ----
        int n2 = n + stride;
        int nc2 = (n2 < n_nodes) ? n2 : n;
        int idx2 = neigh_idx[(size_t)nc2 * K + lane];
        int m2;
        if (byte_mode)
            m2 = ((const unsigned char*)maskbuf)[(size_t)nc2 * K + lane] != 0;
        else
            m2 = ((const unsigned int*)maskbuf)[(size_t)nc2 * K + lane] != 0u;
        int node2 = nodes[nc2];
        uint4 q42 = *(const uint4*)(g_Qb + (size_t)node2 * D + seg * 8);
        uint4 p42[8];
#pragma unroll
        for (int it = 0; it < 8; it++) {
            int ridx = __shfl_sync(0xffffffffu, idx2, it * 4 + rsub);
            p42[it] = *(const uint4*)(g_Pb + (size_t)ridx * D + seg * 8);
        }

        // ---- A fragments (2 m-tiles x 4 k-steps) ----
        uint32_t af[2][4][4];
#pragma unroll
        for (int mt = 0; mt < 2; mt++)
#pragma unroll
            for (int ks = 0; ks < 4; ks++) {
                uint32_t addr = a_base + (mt * 16 + (lane & 15)) * ASTRIDE_B + ks * 32 + (lane >> 4) * 16;
                LDMATRIX_X4(af[mt][ks][0], af[mt][ks][1], af[mt][ks][2], af[mt][ks][3], addr);
            }

        // ---- layer 2 (HMMA) + layer 3 folded per n-tile ----
        float sp0 = 0.f, sp1 = 0.f, sp2 = 0.f, sp3 = 0.f;
#pragma unroll
        for (int nt = 0; nt < 8; nt++) {
            uint32_t b[4][2];
            if (nt < 4) {
#pragma unroll
                for (int ks = 0; ks < 4; ks++) { b[ks][0] = bfh[nt][ks][0]; b[ks][1] = bfh[nt][ks][1]; }
            } else {
                uint32_t r0b, r1b, r2b, r3b;
                uint32_t addr = w_base + lane * ASTRIDE_B + nt * 16;
                LDMATRIX_X4_TRANS(r0b, r1b, r2b, r3b, addr);
                b[0][0] = r0b; b[0][1] = r1b; b[1][0] = r2b; b[1][1] = r3b;
                addr = w_base + (32 + lane) * ASTRIDE_B + nt * 16;
                LDMATRIX_X4_TRANS(r0b, r1b, r2b, r3b, addr);
                b[2][0] = r0b; b[2][1] = r1b; b[3][0] = r2b; b[3][1] = r3b;
            }
            int j = nt * 8 + j0l;
            float bb0 = sb2[j], bb1 = sb2[j + 1];
            float w30 = sW3[j], w31 = sW3[j + 1];
#pragma unroll
            for (int mt = 0; mt < 2; mt++) {
                float d0 = bb0, d1 = bb1, d2 = bb0, d3 = bb1;
#pragma unroll
                for (int ks = 0; ks < 4; ks++)
                    MMA16816(d0, d1, d2, d3,
                             af[mt][ks][0], af[mt][ks][1], af[mt][ks][2], af[mt][ks][3],
                             b[ks][0], b[ks][1]);
                float lo = fmaf(fmaxf(d0, 0.f), w30, fmaf(fmaxf(d1, 0.f), w31, 0.f));
                float hi = fmaf(fmaxf(d2, 0.f), w30, fmaf(fmaxf(d3, 0.f), w31, 0.f));
                if (mt == 0) { sp0 += lo; sp1 += hi; } else { sp2 += lo; sp3 += hi; }
            }
        }

        // ---- early-issue first half of epilogue E gather (depends only on idx) ----
        float4 ev[8];
#pragma unroll
        for (int it = 0; it < 8; it++) {
            int row = it * 2 + erow_sub;
            int ridx = __shfl_sync(0xffffffffu, idx, row);
            ev[it] = *(const float4*)(u2e + (size_t)ridx * D + ecol);
        }

        // ---- finish per-row scores: reduce over the 4 lanes sharing each row ----
        sp0 += __shfl_xor_sync(0xffffffffu, sp0, 1); sp0 += __shfl_xor_sync(0xffffffffu, sp0, 2);
        sp1 += __shfl_xor_sync(0xffffffffu, sp1, 1); sp1 += __shfl_xor_sync(0xffffffffu, sp1, 2);
        sp2 += __shfl_xor_sync(0xffffffffu, sp2, 1); sp2 += __shfl_xor_sync(0xffffffffu, sp2, 2);
        sp3 += __shfl_xor_sync(0xffffffffu, sp3, 1); sp3 += __shfl_xor_sync(0xffffffffu, sp3, 2);

        // ---- distributed masked softmax (no redistribution; b3 softmax-invariant) ----
        unsigned int mask32 = __ballot_sync(0xffffffffu, m);
        float s0 = ((mask32 >> rbase) & 1u)        ? sp0 : -1e30f;
        float s1 = ((mask32 >> (rbase + 8)) & 1u)  ? sp1 : -1e30f;
        float s2 = ((mask32 >> (rbase + 16)) & 1u) ? sp2 : -1e30f;
        float s3 = ((mask32 >> (rbase + 24)) & 1u) ? sp3 : -1e30f;
        float mx = fmaxf(fmaxf(s0, s1), fmaxf(s2, s3));
        mx = fmaxf(mx, __shfl_xor_sync(0xffffffffu, mx, 4));
        mx = fmaxf(mx, __shfl_xor_sync(0xffffffffu, mx, 8));
        mx = fmaxf(mx, __shfl_xor_sync(0xffffffffu, mx, 16));
        float e0 = __expf(s0 - mx), e1 = __expf(s1 - mx);
        float e2 = __expf(s2 - mx), e3 = __expf(s3 - mx);
        float ssum = (e0 + e1) + (e2 + e3);
        ssum += __shfl_xor_sync(0xffffffffu, ssum, 4);
        ssum += __shfl_xor_sync(0xffffffffu, ssum, 8);
        ssum += __shfl_xor_sync(0xffffffffu, ssum, 16);
        float inv = __fdividef(1.f, ssum);
        float att0 = e0 * inv, att1 = e1 * inv, att2 = e2 * inv, att3 = e3 * inv;

        // ---- epilogue: consume prefetched rows 0..15, then gather rows 16..31 ----
        float a0 = 0.f, a1 = 0.f, a2 = 0.f, a3 = 0.f;
#pragma unroll
        for (int it = 0; it < 8; it++) {
            const int oct = it >> 2;
            float att_oct = (oct == 0) ? att0 : att1;
            int row = it * 2 + erow_sub;
            float attr = __shfl_sync(0xffffffffu, att_oct, (row & 7) * 4);
            a0 = fmaf(attr, ev[it].x, a0);
            a1 = fmaf(attr, ev[it].y, a1);
            a2 = fmaf(attr, ev[it].z, a2);
            a3 = fmaf(attr, ev[it].w, a3);
        }
#pragma unroll
        for (int it = 8; it < 16; it++) {
            const int oct = it >> 2;
            float att_oct = (oct == 2) ? att2 : att3;
            int row = it * 2 + erow_sub;
            float attr = __shfl_sync(0xffffffffu, att_oct, (row & 7) * 4);
            int ridx = __shfl_sync(0xffffffffu, idx, row);
            float4 v = *(const float4*)(u2e + (size_t)ridx * D + ecol);
            a0 = fmaf(attr, v.x, a0);
            a1 = fmaf(attr, v.y, a1);
            a2 = fmaf(attr, v.z, a2);
            a3 = fmaf(attr, v.w, a3);
        }
        a0 += __shfl_xor_sync(0xffffffffu, a0, 16);
        a1 += __shfl_xor_sync(0xffffffffu, a1, 16);
        a2 += __shfl_xor_sync(0xffffffffu, a2, 16);
        a3 += __shfl_xor_sync(0xffffffffu, a3, 16);
        if (lane < 16)
            *(float4*)(out + (size_t)n * D + ecol) = make_float4(a0, a1, a2, a3);

        // ---- rotate pipeline registers ----
        idx = idx2; m = m2; q4 = q42;
#pragma unroll
        for (int it = 0; it < 8; it++) p4[it] = p42[it];
    }
}

// ======================= launch =======================
// Input order (metadata): u2e, W1, b1, W2, b2, W3, b3, nodes, neigh_idx, neigh_mask
extern "C" void kernel_launch(void* const* d_in, const int* in_sizes, int n_in,
                              void* d_out, int out_size) {
    const float* u2e = (const float*)d_in[0];
    const float* W1  = (const float*)d_in[1];
    const float* b1  = (const float*)d_in[2];
    const float* W2  = (const float*)d_in[3];
    const float* b2  = (const float*)d_in[4];
    const float* W3  = (const float*)d_in[5];
    const float* b3  = (const float*)d_in[6];
    const int*   nodes     = (const int*)d_in[7];
    const int*   neigh_idx = (const int*)d_in[8];
    const void*  neigh_mask = d_in[9];
    float* out = (float*)d_out;

    int V = in_sizes[0] / D;
    if (V > VOCAB_MAX) V = VOCAB_MAX;
    int n_nodes = in_sizes[7];
    int n_words = in_sizes[9] / 4;   // safe lower bound under both dtypes

    prep_mma_kernel<<<(V + 127) / 128, 128>>>(u2e, W1, b1, V,
                                              (const unsigned int*)neigh_mask, n_words);
    agg_mma_kernel<<<296, 256>>>(u2e, W2, b2, W3, b3,
                                 nodes, neigh_idx, neigh_mask, out, n_nodes);
}